// round 17
// baseline (speedup 1.0000x reference)
#include <cuda_runtime.h>
#include <stdint.h>
#include <math.h>

#define BB   16384
#define HH   256
#define OUTF 256
#define LL   7
#define G4   1024
#define KT   512

// ---------------- scratch (__device__ globals; no allocs allowed) ----------------
__device__ __align__(256) float g_w[(size_t)(LL + 1) * G4 * KT];   // tf32-rounded, gate-reordered, [Wih|Whh] K-concat
__device__ __align__(256) float g_wout[OUTF * HH];                 // tf32-rounded
__device__ __align__(256) float g_bias[(LL + 1) * G4];             // combined (bi+bh), gate-reordered
__device__ __align__(256) float g_x_tf[(size_t)BB * HH];           // tf32-rounded x
__device__ __align__(256) float g_hall_tf[(size_t)(LL + 1) * BB * HH]; // tf32 h_all (slab0 by prep; slabs 1.. by epilogues)
__device__ __align__(256) float g_h_tf[2][(size_t)BB * HH];        // tf32 h ping-pong (layer l writes [l&1])
__device__ int g_bar[128];                                          // per-by-group arrival counters

// ---------------- PTX helpers (arch-portable, sm_80+ baseline) ----------------
__device__ __forceinline__ uint32_t smem_u32(const void* p) {
    uint32_t a;
    asm("{ .reg .u64 t; cvta.to.shared.u64 t, %1; cvt.u32.u64 %0, t; }" : "=r"(a) : "l"(p));
    return a;
}
__device__ __forceinline__ void cp16(uint32_t s, const void* g) {
    asm volatile("cp.async.cg.shared.global [%0], [%1], 16;" :: "r"(s), "l"(g));
}
__device__ __forceinline__ uint32_t lds_u32(uint32_t addr) {
    uint32_t u; asm volatile("ld.shared.b32 %0, [%1];" : "=r"(u) : "r"(addr));
    return u;
}
__device__ __forceinline__ void mma1688(float c[4], const uint32_t a[4],
                                        uint32_t b0, uint32_t b1) {
    asm volatile("mma.sync.aligned.m16n8k8.row.col.f32.tf32.tf32.f32 "
        "{%0,%1,%2,%3}, {%4,%5,%6,%7}, {%8,%9}, {%0,%1,%2,%3};"
        : "+f"(c[0]), "+f"(c[1]), "+f"(c[2]), "+f"(c[3])
        : "r"(a[0]), "r"(a[1]), "r"(a[2]), "r"(a[3]), "r"(b0), "r"(b1));
}
__device__ __forceinline__ float rna_tf32(float x) {
    uint32_t u; asm("cvt.rna.tf32.f32 %0, %1;" : "=r"(u) : "f"(x));
    return __uint_as_float(u);
}
__device__ __forceinline__ float sigf(float x) {
    return __fdividef(1.0f, 1.0f + __expf(-x));
}
__device__ __forceinline__ float tanhfast(float x) {
    return __fdividef(2.0f, 1.0f + __expf(-2.0f * x)) - 1.0f;
}

// ---------------- tile worker: tf32 TN GEMM + optional fused LSTM epilogue ----------------
#define TM 128
#define TN 128
#define NTHREADS 256
#define ROWB 144                           // 128B data + 16B pad
#define STAGE_A (TM * ROWB)                // 18 KB
#define STAGE_B (TN * ROWB)                // 18 KB
#define STAGE   (STAGE_A + STAGE_B)        // 36 KB
#define NSTAGE  3
#define SMEMSZ  (NSTAGE * STAGE)           // 108 KB -> 2 CTAs/SM

template<bool FUSED>
__device__ __forceinline__ void gemm_tile(
    uint32_t sbase, int m0, int n0,
    const float* __restrict__ A1, const float* __restrict__ A2,
    const float* __restrict__ B, int sB, int Ktot,
    const float* __restrict__ bias,
    float* __restrict__ C, int sC,
    const float* __restrict__ c_in, float* __restrict__ h_out, float* __restrict__ c_out,
    float* __restrict__ htf_out,
    const float* __restrict__ hall_next, float* __restrict__ halltf_next)
{
    const int tid  = threadIdx.x;
    const int lane = tid & 31;
    const int wid  = tid >> 5;
    const int wm   = wid & 1;        // 2 warps along M (64 rows)
    const int wn   = wid >> 1;       // 4 warps along N (32 cols)

    const int niter = Ktot >> 5;     // BK = 32

    float c[4][4][4];
    #pragma unroll
    for (int i = 0; i < 4; ++i)
        #pragma unroll
        for (int j = 0; j < 4; ++j)
            #pragma unroll
            for (int q = 0; q < 4; ++q) c[i][j][q] = 0.0f;

    auto load_stage = [&](int buf, int it) {
        const int kc = it << 5;
        const uint32_t sa = sbase + buf * STAGE;
        const uint32_t sb = sa + STAGE_A;
        const float* Asrc; int koff;
        if (kc < 256) { Asrc = A1; koff = kc; } else { Asrc = A2; koff = kc - 256; }
        #pragma unroll
        for (int i = 0; i < 4; ++i) {                    // A: 128 rows x 8 chunks of 16B
            int idx = tid + i * NTHREADS;
            int row = idx >> 3, kg = idx & 7;
            cp16(sa + row * ROWB + (kg << 4),
                 Asrc + (size_t)(m0 + row) * 256 + koff + kg * 4);
        }
        #pragma unroll
        for (int i = 0; i < 4; ++i) {                    // B: 128 rows x 8 chunks
            int idx = tid + i * NTHREADS;
            int row = idx >> 3, kg = idx & 7;
            cp16(sb + row * ROWB + (kg << 4),
                 B + (size_t)(n0 + row) * sB + kc + kg * 4);
        }
        asm volatile("cp.async.commit_group;");
    };

    load_stage(0, 0);
    load_stage(1, 1);

    const int lr = lane >> 2;   // 0..7
    const int lc = lane & 3;    // k-low

    int buf = 0;
    #pragma unroll 1
    for (int i = 0; i < niter; ++i) {
        if (i == niter - 1) asm volatile("cp.async.wait_group 0;");
        else                asm volatile("cp.async.wait_group 1;");
        __syncthreads();
        if (i + 2 < niter) load_stage((buf + 2) % NSTAGE, i + 2);

        const uint32_t sa = sbase + buf * STAGE;
        const uint32_t sb = sa + STAGE_A;
        const uint32_t abase = sa + (wm * 64 + lr) * ROWB + lc * 4;
        const uint32_t bbase = sb + (wn * 32 + lr) * ROWB + lc * 4;

        #pragma unroll
        for (int ks = 0; ks < 4; ++ks) {                 // 4 k8 steps per BK=32
            const int o0 = ks * 32;
            const int o1 = o0 + 16;
            uint32_t a[4][4];
            #pragma unroll
            for (int mi = 0; mi < 4; ++mi) {
                const uint32_t ab = abase + mi * (16 * ROWB);
                a[mi][0] = lds_u32(ab + o0);
                a[mi][1] = lds_u32(ab + 8 * ROWB + o0);
                a[mi][2] = lds_u32(ab + o1);
                a[mi][3] = lds_u32(ab + 8 * ROWB + o1);
            }
            uint32_t b[4][2];
            #pragma unroll
            for (int nj = 0; nj < 4; ++nj) {
                const uint32_t bb = bbase + nj * (8 * ROWB);
                b[nj][0] = lds_u32(bb + o0);
                b[nj][1] = lds_u32(bb + o1);
            }
            #pragma unroll
            for (int mi = 0; mi < 4; ++mi)
                #pragma unroll
                for (int nj = 0; nj < 4; ++nj)
                    mma1688(c[mi][nj], a[mi], b[nj][0], b[nj][1]);
        }
        buf = (buf + 1 == NSTAGE) ? 0 : buf + 1;
    }
    // final sync so smem is safe for the next layer's prologue loads
    __syncthreads();

    if (!FUSED) {
        #pragma unroll
        for (int mi = 0; mi < 4; ++mi) {
            const int r0 = m0 + wm * 64 + mi * 16 + lr;
            #pragma unroll
            for (int nj = 0; nj < 4; ++nj) {
                const int col = n0 + wn * 32 + nj * 8 + lc * 2;
                float bx = bias[col], by = bias[col + 1];
                *(float2*)&C[(size_t)r0 * sC + col] =
                    make_float2(c[mi][nj][0] + bx, c[mi][nj][1] + by);
                *(float2*)&C[(size_t)(r0 + 8) * sC + col] =
                    make_float2(c[mi][nj][2] + bx, c[mi][nj][3] + by);
            }
        }
    } else {
        // fused LSTM epilogue (gate-reordered cols: thread's 4 nj = gates i,f,g,o of
        // units ub, ub+1). Writes h/c fp32, tf32 h to ping-pong, pre-rounds next h_all.
        const int ub = ((n0 + wn * 32) >> 2) + (lc << 1);
        float bsv[4][2];
        #pragma unroll
        for (int g = 0; g < 4; ++g) {
            bsv[g][0] = bias[n0 + wn * 32 + g * 8 + lc * 2];
            bsv[g][1] = bias[n0 + wn * 32 + g * 8 + lc * 2 + 1];
        }
        #pragma unroll
        for (int mi = 0; mi < 4; ++mi) {
            #pragma unroll
            for (int rh = 0; rh < 2; ++rh) {
                const int row = m0 + wm * 64 + mi * 16 + rh * 8 + lr;
                const float2 cin = *(const float2*)&c_in[(size_t)row * HH + ub];
                float hv[2], cv[2];
                #pragma unroll
                for (int e = 0; e < 2; ++e) {
                    const int q = rh * 2 + e;
                    float gi = sigf    (c[mi][0][q] + bsv[0][e]);
                    float gf = sigf    (c[mi][1][q] + bsv[1][e]);
                    float gg = tanhfast(c[mi][2][q] + bsv[2][e]);
                    float go = sigf    (c[mi][3][q] + bsv[3][e]);
                    float ci = e ? cin.y : cin.x;
                    cv[e] = gf * ci + gi * gg;
                    hv[e] = go * tanhfast(cv[e]);
                }
                *(float2*)&c_out[(size_t)row * HH + ub] = make_float2(cv[0], cv[1]);
                *(float2*)&h_out[(size_t)row * HH + ub] = make_float2(hv[0], hv[1]);
                *(float2*)&htf_out[(size_t)row * HH + ub] =
                    make_float2(rna_tf32(hv[0]), rna_tf32(hv[1]));
                if (hall_next) {
                    const float2 hn = *(const float2*)&hall_next[(size_t)row * HH + ub];
                    *(float2*)&halltf_next[(size_t)row * HH + ub] =
                        make_float2(rna_tf32(hn.x), rna_tf32(hn.y));
                }
            }
        }
    }
}

// ---------------- persistent kernel: 8 LSTM layers + output GEMM, one launch ----------------
// Grid (8, 128). Dependencies are per by-row-group: layer l+1 tile (.,by) needs only
// the 8 CTAs (bx=0..7, by) of layer l -> 8-CTA group barrier on g_bar[by].
__global__ void __launch_bounds__(NTHREADS, 2) lstm_persistent(
    const float* __restrict__ x_tf, const float* __restrict__ hall,
    const float* __restrict__ c_all,
    float* __restrict__ out, float* __restrict__ hs, float* __restrict__ cs)
{
    extern __shared__ __align__(128) char dsm[];
    const uint32_t sbase = smem_u32(dsm);
    const int bx = blockIdx.x;        // 0..7  (n-tile)
    const int by = blockIdx.y;        // 0..127 (m-tile / row group)
    const int m0 = by * TM;
    const int n0 = bx * TN;
    const int tid = threadIdx.x;

    float* htfb[2] = { g_h_tf[0], g_h_tf[1] };

    #pragma unroll 1
    for (int l = 0; l <= LL; ++l) {
        const float* a1      = (l == 0) ? x_tf : htfb[(l - 1) & 1];
        const float* hnext   = (l < LL) ? hall + (size_t)(l + 1) * BB * HH : nullptr;
        float*       hnexttf = (l < LL) ? g_hall_tf + (size_t)(l + 1) * BB * HH : nullptr;

        gemm_tile<true>(sbase, m0, n0,
            a1, g_hall_tf + (size_t)l * BB * HH,
            g_w + (size_t)l * G4 * KT, KT, KT,
            g_bias + (size_t)l * G4,
            nullptr, 0,
            c_all + (size_t)l * BB * HH,
            hs + (size_t)l * BB * HH, cs + (size_t)l * BB * HH,
            htfb[l & 1], hnext, hnexttf);

        // group barrier: release (all epilogue stores -> L2) then arrive
        __syncthreads();
        if (tid == 0) {
            __threadfence();
            atomicAdd(&g_bar[by], 1);
        }
        const bool needs_next = (l < LL) || (bx < 2);
        if (!needs_next) return;                 // bx>=2 done after final arrival
        if (tid == 0) {
            const int target = 8 * (l + 1);
            while (*(volatile int*)&g_bar[by] < target) __nanosleep(64);
        }
        __syncthreads();                          // all threads see the observation
        // consumers read htf/halltf exclusively via cp.async.cg (L2-direct) -> coherent
    }

    // output GEMM: out = h7 @ Wout.T + bout   (bx<2 cover all 256 cols; K=256)
    gemm_tile<false>(sbase, m0, n0,
        htfb[LL & 1], nullptr,
        g_wout, HH, HH,
        g_bias /*unused*/, nullptr, 0,
        nullptr, nullptr, nullptr, nullptr, nullptr, nullptr);
}

// overload-free plain epilogue needs bias/C; re-dispatch with correct args:
// (handled by passing bias=bout, C=out below via a thin wrapper kernel param path)
// -> we instead specialize: see launch (bias/out passed through globals is avoided by
//    calling gemm_tile<false> with real pointers):
__global__ void __launch_bounds__(NTHREADS, 2) lstm_persistent_full(
    const float* __restrict__ x_tf, const float* __restrict__ hall,
    const float* __restrict__ c_all, const float* __restrict__ bout,
    float* __restrict__ out, float* __restrict__ hs, float* __restrict__ cs)
{
    extern __shared__ __align__(128) char dsm[];
    const uint32_t sbase = smem_u32(dsm);
    const int bx = blockIdx.x;
    const int by = blockIdx.y;
    const int m0 = by * TM;
    const int n0 = bx * TN;
    const int tid = threadIdx.x;

    float* htfb[2] = { g_h_tf[0], g_h_tf[1] };

    #pragma unroll 1
    for (int l = 0; l <= LL; ++l) {
        const float* a1      = (l == 0) ? x_tf : htfb[(l - 1) & 1];
        const float* hnext   = (l < LL) ? hall + (size_t)(l + 1) * BB * HH : nullptr;
        float*       hnexttf = (l < LL) ? g_hall_tf + (size_t)(l + 1) * BB * HH : nullptr;

        gemm_tile<true>(sbase, m0, n0,
            a1, g_hall_tf + (size_t)l * BB * HH,
            g_w + (size_t)l * G4 * KT, KT, KT,
            g_bias + (size_t)l * G4,
            nullptr, 0,
            c_all + (size_t)l * BB * HH,
            hs + (size_t)l * BB * HH, cs + (size_t)l * BB * HH,
            htfb[l & 1], hnext, hnexttf);

        __syncthreads();
        if (tid == 0) {
            __threadfence();
            atomicAdd(&g_bar[by], 1);
        }
        const bool needs_next = (l < LL) || (bx < 2);
        if (!needs_next) return;
        if (tid == 0) {
            const int target = 8 * (l + 1);
            while (*(volatile int*)&g_bar[by] < target) __nanosleep(64);
        }
        __syncthreads();
    }

    gemm_tile<false>(sbase, m0, n0,
        htfb[LL & 1], nullptr,
        g_wout, HH, HH,
        bout,
        out, OUTF,
        nullptr, nullptr, nullptr, nullptr, nullptr, nullptr);
}

// ---------------- prep kernels (once per call) ----------------
__global__ void __launch_bounds__(256) conv_w(
    const float* __restrict__ Wih0, const float* __restrict__ Whh0,
    const float* __restrict__ Wih,  const float* __restrict__ Whh)
{
    int t  = blockIdx.x * blockDim.x + threadIdx.x;     // 1048576
    int k4 = (t & 127) << 2;
    int nn = (t >> 7) & 1023;
    int l  = t >> 17;
    int gate = (nn >> 3) & 3;
    int unit = ((nn >> 5) << 3) + (nn & 7);
    int no   = gate * 256 + unit;
    const float* src;
    if (l == 0) src = (k4 < 256) ? (Wih0 + (size_t)no * 256 + k4)
                                 : (Whh0 + (size_t)no * 256 + (k4 - 256));
    else        src = (k4 < 256) ? (Wih + ((size_t)(l - 1) * G4 + no) * 256 + k4)
                                 : (Whh + ((size_t)(l - 1) * G4 + no) * 256 + (k4 - 256));
    float4 v = *(const float4*)src;
    v.x = rna_tf32(v.x); v.y = rna_tf32(v.y); v.z = rna_tf32(v.z); v.w = rna_tf32(v.w);
    *(float4*)&g_w[((size_t)l * G4 + nn) * KT + k4] = v;
}

__global__ void __launch_bounds__(256) conv_wout(const float* __restrict__ Wout) {
    int t = blockIdx.x * blockDim.x + threadIdx.x;      // 16384
    int n = t >> 6, k4 = (t & 63) << 2;
    float4 v = *(const float4*)(Wout + (size_t)n * HH + k4);
    v.x = rna_tf32(v.x); v.y = rna_tf32(v.y); v.z = rna_tf32(v.z); v.w = rna_tf32(v.w);
    *(float4*)&g_wout[(size_t)n * HH + k4] = v;
}

__global__ void __launch_bounds__(256) conv_bias(
    const float* __restrict__ bih0, const float* __restrict__ bhh0,
    const float* __restrict__ bih,  const float* __restrict__ bhh)
{
    int t  = blockIdx.x * blockDim.x + threadIdx.x;     // 8192
    int nn = t & 1023;
    int l  = t >> 10;
    int gate = (nn >> 3) & 3;
    int unit = ((nn >> 5) << 3) + (nn & 7);
    int no   = gate * 256 + unit;
    float v;
    if (l == 0) v = bih0[no] + bhh0[no];
    else        v = bih[(size_t)(l - 1) * G4 + no] + bhh[(size_t)(l - 1) * G4 + no];
    g_bias[t] = v;
    if (t < 128) g_bar[t] = 0;                           // reset group barriers every replay
}

__global__ void __launch_bounds__(256) round_tf(const float* __restrict__ src,
                                                float* __restrict__ dst) {
    size_t t = (size_t)blockIdx.x * blockDim.x + threadIdx.x;
    float4 v = *(const float4*)(src + t * 4);
    v.x = rna_tf32(v.x); v.y = rna_tf32(v.y); v.z = rna_tf32(v.z); v.w = rna_tf32(v.w);
    *(float4*)(dst + t * 4) = v;
}

// ---------------- launch ----------------
extern "C" void kernel_launch(void* const* d_in, const int* in_sizes, int n_in,
                              void* d_out, int out_size)
{
    const float* x     = (const float*)d_in[0];
    const float* h_all = (const float*)d_in[1];
    const float* c_all = (const float*)d_in[2];
    const float* Wih0  = (const float*)d_in[3];
    const float* Whh0  = (const float*)d_in[4];
    const float* bih0  = (const float*)d_in[5];
    const float* bhh0  = (const float*)d_in[6];
    const float* Wih   = (const float*)d_in[7];
    const float* Whh   = (const float*)d_in[8];
    const float* bih   = (const float*)d_in[9];
    const float* bhh   = (const float*)d_in[10];
    const float* Wout  = (const float*)d_in[11];
    const float* bout  = (const float*)d_in[12];

    float* out = (float*)d_out;
    float* hs  = out + (size_t)BB * OUTF;
    float* cs  = hs + (size_t)(LL + 1) * BB * HH;

    float *xtf, *halltf;
    cudaGetSymbolAddress((void**)&xtf,    g_x_tf);
    cudaGetSymbolAddress((void**)&halltf, g_hall_tf);

    cudaFuncSetAttribute(lstm_persistent_full,
                         cudaFuncAttributeMaxDynamicSharedMemorySize, SMEMSZ);

    conv_w<<<4096, 256>>>(Wih0, Whh0, Wih, Whh);
    conv_wout<<<64, 256>>>(Wout);
    conv_bias<<<32, 256>>>(bih0, bhh0, bih, bhh);        // also zeroes g_bar
    round_tf<<<(BB * HH / 4) / 256, 256>>>(x, xtf);
    round_tf<<<(BB * HH / 4) / 256, 256>>>(h_all, halltf);   // slab 0 only

    lstm_persistent_full<<<dim3(8, 128), NTHREADS, SMEMSZ>>>(
        xtf, h_all, c_all, bout, out, hs, cs);
}